// round 6
// baseline (speedup 1.0000x reference)
#include <cuda_runtime.h>
#include <stdint.h>

#define NC   151          // classes incl. background
#define CM1  150
#define DIM  2048
#define NB   128          // images
#define NP   512          // pairs per image
#define CAP  16           // max absent classes handled in smem (fallback beyond)
#define CHW  16           // float4 per chunk row (64 floats)
#define NCHUNK (DIM / 4 / CHW)   // 32
#define TPB  1024

// ---------------- device scratch ----------------
__device__ float g_sym[NC * NC];
__device__ float g_T0[NC * DIM];
__device__ float g_T1[NC * DIM];
__device__ int   g_abs_cnt[NB];
__device__ int   g_abs_list[NB * CM1];

// ---------------- float4 helpers ----------------
__device__ __forceinline__ float4 f4add(float4 a, float4 b) {
    return make_float4(a.x + b.x, a.y + b.y, a.z + b.z, a.w + b.w);
}
__device__ __forceinline__ float4 f4fms(float s, float4 a, float4 acc) {
    acc.x = fmaf(-s, a.x, acc.x); acc.y = fmaf(-s, a.y, acc.y);
    acc.z = fmaf(-s, a.z, acc.z); acc.w = fmaf(-s, a.w, acc.w);
    return acc;
}

// int64-vs-int32 detection (all pair values >= 1, little-endian)
__device__ __forceinline__ int pairs_is64(const int* p32) { return (p32[1] == 0) ? 1 : 0; }

// ---------------- kernel 1: fused prep (all block roles independent) ----------------
// block 0            : sym table
// blocks 1..NB       : per-image absent lists
// blocks NB+1 ...    : T0/T1 tables, reading lin_w natively (no transpose)
//                      decode t = bx-NB-1: cgrp=t%19 (8 classes), which=(t/19)%2,
//                      dwin=t/38 (8 windows of 256 d). 256 threads, thread owns one d.
__global__ void k_pre(const void* __restrict__ pairs_v,
                      const float* __restrict__ score,
                      const float* __restrict__ w,
                      const float* __restrict__ lb) {
    const int* p32 = (const int*)pairs_v;
    int tid = threadIdx.x;
    if (blockIdx.x == 0) {
        for (int idx = tid; idx < NC * NC; idx += blockDim.x) {
            int c = idx / NC, e = idx % NC;
            g_sym[idx] = 0.5f * (score[c * NC + e] + score[e * NC + c]);
        }
    } else if (blockIdx.x <= NB) {
        int b = blockIdx.x - 1;
        int is64 = pairs_is64(p32);
        __shared__ int flags[NC];
        for (int i = tid; i < NC; i += blockDim.x) flags[i] = 0;
        __syncthreads();
        for (int i = tid; i < 2 * NP; i += blockDim.x) {
            size_t ei = (size_t)b * 2 * NP + i;
            flags[p32[ei << is64]] = 1;
        }
        __syncthreads();
        if (tid == 0) {
            int cnt = 0;
            for (int e = 1; e < NC; ++e)
                if (!flags[e]) g_abs_list[b * CM1 + cnt++] = e;
            g_abs_cnt[b] = cnt;
        }
    } else {
        int t = blockIdx.x - (NB + 1);
        int cBase = (t % 19) * 8;
        int which = (t / 19) & 1;
        int dwin  = t / 38;                       // 0..7
        __shared__ float ssym[8][NC + 1];
        // local sym rows straight from score (no dependency on block 0)
        for (int idx = tid; idx < 8 * NC; idx += 256) {
            int ci = idx / NC, e = idx % NC;
            int c = cBase + ci;
            ssym[ci][e] = (c < NC) ? 0.5f * (score[c * NC + e] + score[e * NC + c]) : 0.f;
        }
        __syncthreads();
        int d = dwin * 256 + tid;                 // 0..2047, thread owns one output d
        const float* wr = w + (size_t)d * 600 + which * CM1;  // cols base..base+149, 8B aligned
        float acc[8];
#pragma unroll
        for (int ci = 0; ci < 8; ++ci) acc[ci] = 0.f;
#pragma unroll 4
        for (int ee = 0; ee < CM1; ee += 2) {     // e = ee+1, ee+2
            float2 wv = *(const float2*)(wr + ee);
#pragma unroll
            for (int ci = 0; ci < 8; ++ci)
                acc[ci] = fmaf(ssym[ci][ee + 1], wv.x, fmaf(ssym[ci][ee + 2], wv.y, acc[ci]));
        }
        float hb = 0.5f * lb[d];
        float* Tdst = which ? g_T1 : g_T0;
#pragma unroll
        for (int ci = 0; ci < 8; ++ci) {
            int c = cBase + ci;
            if (c >= NC) continue;
            float v = acc[ci] + hb;
            if (c >= 1) v += w[(size_t)d * 600 + 300 + which * CM1 + c - 1];
            Tdst[(size_t)c * DIM + d] = v;
        }
    }
}

// ---------------- rare exact fallback (keeps main loop register-lean) ----------------
__device__ __noinline__ float4 fallback_corr(float4 v, const float* __restrict__ lw,
                                             int b, int p0, int p1,
                                             int cb, int j, int cnt) {
    int dbase = (cb + j) * 4;
    for (int k = CAP; k < cnt; ++k) {
        int e = g_abs_list[b * CM1 + k];
        float c0 = g_sym[p0 * NC + e];
        float c1 = g_sym[p1 * NC + e];
#pragma unroll
        for (int dd = 0; dd < 4; ++dd) {
            float a  = lw[(size_t)(dbase + dd) * 600 + (e - 1)];
            float bb = lw[(size_t)(dbase + dd) * 600 + (CM1 + e - 1)];
            float* vc = ((float*)&v) + dd;
            *vc = fmaf(-c0, a, fmaf(-c1, bb, *vc));
        }
    }
    return v;
}

// ---------------- kernel 2: persistent gather/add ----------------
// grid 296 (2 blocks/SM), 1024 threads, ~99.4KB dynamic smem each.
__global__ void __launch_bounds__(TPB, 2) k_main(const void* __restrict__ pairs_v,
                                                 const float* __restrict__ lw,
                                                 float* __restrict__ out) {
    extern __shared__ float4 smem[];
    float4* s0 = smem;                       // NC*CHW float4
    float4* s1 = s0 + NC * CHW;              // NC*CHW
    float4* wa = s1 + NC * CHW;              // CAP*CHW
    float4* wb = wa + CAP * CHW;             // CAP*CHW
    float* scorr = (float*)(wb + CAP * CHW); // CAP*NC floats
    int* sp = (int*)(scorr + CAP * NC);      // 2*NP = 1024
    int* slist = sp + 2 * NP;                // CAP
    __shared__ int scnt;

    const int* p32 = (const int*)pairs_v;
    int is64 = pairs_is64(p32);
    int tid = threadIdx.x;
    const float4* T04 = (const float4*)g_T0;
    const float4* T14 = (const float4*)g_T1;
    float4* out4 = (float4*)out;

    const int nitems = NCHUNK * NB;          // 4096
    int start = (int)(((long)nitems * blockIdx.x) / gridDim.x);
    int end   = (int)(((long)nitems * (blockIdx.x + 1)) / gridDim.x);
    int cur_chunk = -1;

    for (int item = start; item < end; ++item) {
        int chunk = item >> 7;               // item / NB
        int b = item & (NB - 1);
        int cb = chunk * CHW;

        __syncthreads();                     // protect smem reuse from prior item
        if (chunk != cur_chunk) {
            for (int idx = tid; idx < NC * CHW; idx += TPB) {
                int c = idx / CHW, j = idx % CHW;
                s0[idx] = T04[(size_t)c * (DIM / 4) + cb + j];
                s1[idx] = T14[(size_t)c * (DIM / 4) + cb + j];
            }
            cur_chunk = chunk;
        }
        sp[tid] = p32[((size_t)b * 2 * NP + tid) << is64];
        if (tid < CAP) slist[tid] = g_abs_list[b * CM1 + tid];
        if (tid == 0) scnt = g_abs_cnt[b];
        __syncthreads();

        int cnt = scnt;
        int kc = cnt < CAP ? cnt : CAP;
        // correction weights: wa/wb[k][dd] = lin_w[d][e-1], d = cb*4+dd (dd<64)
        float* waf = (float*)wa;
        float* wbf = (float*)wb;
        for (int idx = tid; idx < kc * 64; idx += TPB) {
            int k = idx >> 6, dd = idx & 63;
            int e = slist[k];
            const float* row = lw + (size_t)(cb * 4 + dd) * 600;
            waf[k * 64 + dd] = row[e - 1];
            wbf[k * 64 + dd] = row[CM1 + e - 1];
        }
        // correction coefficients: scorr[k][c] = sym[c][e_k]
        for (int idx = tid; idx < kc * NC; idx += TPB) {
            int k = idx / NC, c = idx - k * NC;
            scorr[k * NC + c] = g_sym[c * NC + slist[k]];
        }
        if (kc) __syncthreads();

        int j = tid & (CHW - 1), sub = tid >> 4;   // sub in 0..63
#pragma unroll 4
        for (int it = 0; it < NP / 64; ++it) {
            int p = it * 64 + sub;
            int p0 = sp[2 * p], p1 = sp[2 * p + 1];
            float4 v = f4add(s0[p0 * CHW + j], s1[p1 * CHW + j]);
            for (int k = 0; k < kc; ++k) {
                v = f4fms(scorr[k * NC + p0], wa[k * CHW + j], v);
                v = f4fms(scorr[k * NC + p1], wb[k * CHW + j], v);
            }
            if (cnt > CAP) v = fallback_corr(v, lw, b, p0, p1, cb, j, cnt);
            __stcs(&out4[(size_t)(b * NP + p) * (DIM / 4) + cb + j], v);
        }
    }
}

// ---------------- launch ----------------
static const size_t SMEM_MAIN =
    (size_t)(2 * NC * CHW + 2 * CAP * CHW) * sizeof(float4)
    + (size_t)CAP * NC * sizeof(float)
    + (2 * NP + CAP) * sizeof(int);

extern "C" void kernel_launch(void* const* d_in, const int* in_sizes, int n_in,
                              void* d_out, int out_size) {
    const void*  pairs = d_in[0];
    const float* score = (const float*)d_in[1];
    const float* lw    = (const float*)d_in[2];
    const float* lb    = (const float*)d_in[3];
    float* out = (float*)d_out;
    (void)in_sizes; (void)n_in; (void)out_size;

    cudaFuncSetAttribute(k_main, cudaFuncAttributeMaxDynamicSharedMemorySize, (int)SMEM_MAIN);

    k_pre <<<NB + 1 + 19 * 2 * 8, 256>>>(pairs, score, lw, lb);
    k_main<<<296, TPB, SMEM_MAIN>>>(pairs, lw, out);
}

// round 7
// speedup vs baseline: 1.1113x; 1.1113x over previous
#include <cuda_runtime.h>
#include <stdint.h>

#define NC   151          // classes incl. background
#define CM1  150
#define DIM  2048
#define NB   128          // images
#define NP   512          // pairs per image
#define CAP  16           // max absent classes handled in smem (fallback beyond)
#define CHW  16           // float4 per chunk row (64 floats)
#define NCHUNK (DIM / 4 / CHW)   // 32
#define TPB  1024

// ---------------- device scratch ----------------
__device__ float g_sym[NC * NC];
__device__ float g_WT[600 * DIM];         // lin_w transposed
__device__ float g_T0[NC * DIM];
__device__ float g_T1[NC * DIM];
__device__ int   g_abs_cnt[NB];
__device__ int   g_abs_list[NB * CM1];

// ---------------- float4 helpers ----------------
__device__ __forceinline__ float4 f4add(float4 a, float4 b) {
    return make_float4(a.x + b.x, a.y + b.y, a.z + b.z, a.w + b.w);
}
__device__ __forceinline__ float4 f4fma(float s, float4 a, float4 acc) {
    acc.x = fmaf(s, a.x, acc.x); acc.y = fmaf(s, a.y, acc.y);
    acc.z = fmaf(s, a.z, acc.z); acc.w = fmaf(s, a.w, acc.w);
    return acc;
}
__device__ __forceinline__ float4 f4fms(float s, float4 a, float4 acc) {
    acc.x = fmaf(-s, a.x, acc.x); acc.y = fmaf(-s, a.y, acc.y);
    acc.z = fmaf(-s, a.z, acc.z); acc.w = fmaf(-s, a.w, acc.w);
    return acc;
}

// int64-vs-int32 detection (all pair values >= 1, little-endian)
__device__ __forceinline__ int pairs_is64(const int* p32) { return (p32[1] == 0) ? 1 : 0; }

// ---------------- kernel 1: fused sym + absent lists + weight transpose ----------------
__global__ void k_setup(const void* __restrict__ pairs_v,
                        const float* __restrict__ score,
                        const float* __restrict__ w) {
    const int* p32 = (const int*)pairs_v;
    int tid = threadIdx.x;
    if (blockIdx.x == 0) {
        for (int idx = tid; idx < NC * NC; idx += blockDim.x) {
            int c = idx / NC, e = idx % NC;
            g_sym[idx] = 0.5f * (score[c * NC + e] + score[e * NC + c]);
        }
    } else if (blockIdx.x <= NB) {
        int b = blockIdx.x - 1;
        int is64 = pairs_is64(p32);
        __shared__ int flags[NC];
        for (int i = tid; i < NC; i += blockDim.x) flags[i] = 0;
        __syncthreads();
        for (int i = tid; i < 2 * NP; i += blockDim.x) {
            size_t ei = (size_t)b * 2 * NP + i;
            flags[p32[ei << is64]] = 1;
        }
        __syncthreads();
        if (tid == 0) {
            int cnt = 0;
            for (int e = 1; e < NC; ++e)
                if (!flags[e]) g_abs_list[b * CM1 + cnt++] = e;
            g_abs_cnt[b] = cnt;
        }
    } else {
        // transpose tile: lin_w [2048,600] -> WT [600,2048]
        int t_id = blockIdx.x - (NB + 1);        // 0 .. 19*64-1
        int j0 = (t_id % 19) * 32, d0 = (t_id / 19) * 32;
        __shared__ float t[32][33];
        int tx = tid & 31, ty = tid >> 5;        // 256 threads -> (32, 8)
        for (int r = ty; r < 32; r += 8) {
            int d = d0 + r, j = j0 + tx;
            t[r][tx] = (j < 600) ? w[(size_t)d * 600 + j] : 0.f;
        }
        __syncthreads();
        for (int r = ty; r < 32; r += 8) {
            int j = j0 + r;
            if (j < 600) g_WT[(size_t)j * DIM + d0 + tx] = t[tx][r];
        }
    }
}

// ---------------- kernel 2: dense class tables T0/T1 ----------------
// grid (38, 2, 4), block 128. 4 classes x 128 float4-cols per block; e-loop
// unrolled x6 for memory-level parallelism.
__global__ void k_tables(const float* __restrict__ lb) {
    int which = blockIdx.y;
    int cBase = blockIdx.x * 4;
    __shared__ float ssym[4][NC + 1];
    int tid = threadIdx.x;
    for (int idx = tid; idx < 4 * NC; idx += 128) {
        int ci = idx / NC, e = idx % NC;
        int c = cBase + ci;
        ssym[ci][e] = (c < NC) ? g_sym[c * NC + e] : 0.f;
    }
    __syncthreads();
    const float4* WT4 = (const float4*)g_WT;
    int d4 = blockIdx.z * 128 + tid;             // 0..511
    float4 acc[4];
#pragma unroll
    for (int ci = 0; ci < 4; ++ci) acc[ci] = make_float4(0.f, 0.f, 0.f, 0.f);
    int base = which * CM1;
#pragma unroll 6
    for (int e = 1; e < NC; ++e) {
        float4 wv = WT4[(size_t)(base + e - 1) * (DIM / 4) + d4];
#pragma unroll
        for (int ci = 0; ci < 4; ++ci) acc[ci] = f4fma(ssym[ci][e], wv, acc[ci]);
    }
    float4 hb = ((const float4*)lb)[d4];
    hb.x *= 0.5f; hb.y *= 0.5f; hb.z *= 0.5f; hb.w *= 0.5f;
    float* Tdst = which ? g_T1 : g_T0;
#pragma unroll
    for (int ci = 0; ci < 4; ++ci) {
        int c = cBase + ci;
        if (c >= NC) continue;
        float4 v = f4add(acc[ci], hb);
        if (c >= 1) {
            float4 pv = WT4[(size_t)(300 + which * CM1 + c - 1) * (DIM / 4) + d4];
            v = f4add(v, pv);
        }
        ((float4*)Tdst)[(size_t)c * (DIM / 4) + d4] = v;
    }
}

// ---------------- rare exact fallback (keeps main loop register-lean) ----------------
__device__ __noinline__ float4 fallback_corr(float4 v, int b, int p0, int p1,
                                             int cb, int j, int cnt) {
    const float4* WT4 = (const float4*)g_WT;
    for (int k = CAP; k < cnt; ++k) {
        int e = g_abs_list[b * CM1 + k];
        float4 a  = WT4[(size_t)(e - 1) * (DIM / 4) + cb + j];
        float4 bb = WT4[(size_t)(CM1 + e - 1) * (DIM / 4) + cb + j];
        v = f4fms(g_sym[p0 * NC + e], a, v);
        v = f4fms(g_sym[p1 * NC + e], bb, v);
    }
    return v;
}

// ---------------- kernel 3: persistent gather/add ----------------
// grid 296 (2 blocks/SM = 2048 threads/SM cap), ~89.7KB dynamic smem each.
__global__ void __launch_bounds__(TPB, 2) k_main(const void* __restrict__ pairs_v,
                                                 float* __restrict__ out) {
    extern __shared__ float4 smem[];
    float4* s0 = smem;                       // NC*CHW
    float4* s1 = s0 + NC * CHW;              // NC*CHW
    float4* wa = s1 + NC * CHW;              // CAP*CHW
    float4* wb = wa + CAP * CHW;             // CAP*CHW
    int* sp = (int*)(wb + CAP * CHW);        // 2*NP = 1024
    int* slist = sp + 2 * NP;                // CAP
    __shared__ int scnt;

    const int* p32 = (const int*)pairs_v;
    int is64 = pairs_is64(p32);
    int tid = threadIdx.x;
    const float4* T04 = (const float4*)g_T0;
    const float4* T14 = (const float4*)g_T1;
    const float4* WT4 = (const float4*)g_WT;
    float4* out4 = (float4*)out;

    const int nitems = NCHUNK * NB;          // 4096
    int start = (int)(((long)nitems * blockIdx.x) / gridDim.x);
    int end   = (int)(((long)nitems * (blockIdx.x + 1)) / gridDim.x);
    int cur_chunk = -1;

    for (int item = start; item < end; ++item) {
        int chunk = item >> 7;               // item / NB
        int b = item & (NB - 1);
        int cb = chunk * CHW;

        __syncthreads();                     // protect smem reuse from prior item
        if (chunk != cur_chunk) {
            for (int idx = tid; idx < NC * CHW; idx += TPB) {
                int c = idx / CHW, j = idx % CHW;
                s0[idx] = T04[(size_t)c * (DIM / 4) + cb + j];
                s1[idx] = T14[(size_t)c * (DIM / 4) + cb + j];
            }
            cur_chunk = chunk;
        }
        sp[tid] = p32[((size_t)b * 2 * NP + tid) << is64];
        if (tid < CAP) slist[tid] = g_abs_list[b * CM1 + tid];
        if (tid == 0) scnt = g_abs_cnt[b];
        __syncthreads();

        int cnt = scnt;
        int kc = cnt < CAP ? cnt : CAP;
        for (int idx = tid; idx < kc * CHW; idx += TPB) {
            int k = idx / CHW, j = idx % CHW;
            int e = slist[k];
            wa[idx] = WT4[(size_t)(e - 1) * (DIM / 4) + cb + j];
            wb[idx] = WT4[(size_t)(CM1 + e - 1) * (DIM / 4) + cb + j];
        }
        if (kc) __syncthreads();

        int j = tid & (CHW - 1), sub = tid >> 4;   // sub in 0..63
#pragma unroll 4
        for (int it = 0; it < NP / 64; ++it) {
            int p = it * 64 + sub;
            int p0 = sp[2 * p], p1 = sp[2 * p + 1];
            float4 v = f4add(s0[p0 * CHW + j], s1[p1 * CHW + j]);
            for (int k = 0; k < kc; ++k) {
                int e = slist[k];
                v = f4fms(g_sym[p0 * NC + e], wa[k * CHW + j], v);
                v = f4fms(g_sym[p1 * NC + e], wb[k * CHW + j], v);
            }
            if (cnt > CAP) v = fallback_corr(v, b, p0, p1, cb, j, cnt);
            out4[(size_t)(b * NP + p) * (DIM / 4) + cb + j] = v;   // plain STG.128
        }
    }
}

// ---------------- launch ----------------
static const size_t SMEM_MAIN =
    (size_t)(2 * NC * CHW + 2 * CAP * CHW) * sizeof(float4) + (2 * NP + CAP) * sizeof(int);

extern "C" void kernel_launch(void* const* d_in, const int* in_sizes, int n_in,
                              void* d_out, int out_size) {
    const void*  pairs = d_in[0];
    const float* score = (const float*)d_in[1];
    const float* lw    = (const float*)d_in[2];
    const float* lb    = (const float*)d_in[3];
    float* out = (float*)d_out;
    (void)in_sizes; (void)n_in; (void)out_size;

    cudaFuncSetAttribute(k_main, cudaFuncAttributeMaxDynamicSharedMemorySize, (int)SMEM_MAIN);

    k_setup <<<NB + 1 + 19 * 64, 256>>>(pairs, score, lw);
    k_tables<<<dim3(38, 2, 4), 128>>>(lb);
    k_main  <<<296, TPB, SMEM_MAIN>>>(pairs, out);
}

// round 8
// speedup vs baseline: 1.1962x; 1.0764x over previous
#include <cuda_runtime.h>
#include <stdint.h>

#define NC   151          // classes incl. background
#define CM1  150
#define DIM  2048
#define NB   128          // images
#define NP   512          // pairs per image
#define CAP  16           // max absent classes handled in smem (fallback beyond)
#define CHW  16           // float4 per chunk row (64 floats)
#define NCHUNK (DIM / 4 / CHW)   // 32
#define TPB  1024
#define NJT  19           // ceil(600/32) j-tiles
#define NDT  16           // 2048/128 d-tiles

// ---------------- device scratch ----------------
__device__ float g_sym[NC * NC];
__device__ float g_WT[600 * DIM];         // lin_w transposed
__device__ float g_T0[NC * DIM];
__device__ float g_T1[NC * DIM];
__device__ int   g_abs_cnt[NB];
__device__ int   g_abs_list[NB * CM1];

// ---------------- float4 helpers ----------------
__device__ __forceinline__ float4 f4add(float4 a, float4 b) {
    return make_float4(a.x + b.x, a.y + b.y, a.z + b.z, a.w + b.w);
}
__device__ __forceinline__ float4 f4fma(float s, float4 a, float4 acc) {
    acc.x = fmaf(s, a.x, acc.x); acc.y = fmaf(s, a.y, acc.y);
    acc.z = fmaf(s, a.z, acc.z); acc.w = fmaf(s, a.w, acc.w);
    return acc;
}
__device__ __forceinline__ float4 f4fms(float s, float4 a, float4 acc) {
    acc.x = fmaf(-s, a.x, acc.x); acc.y = fmaf(-s, a.y, acc.y);
    acc.z = fmaf(-s, a.z, acc.z); acc.w = fmaf(-s, a.w, acc.w);
    return acc;
}

// int64-vs-int32 detection (all pair values >= 1, little-endian)
__device__ __forceinline__ int pairs_is64(const int* p32) { return (p32[1] == 0) ? 1 : 0; }

// ---------------- kernel 1: fused sym + absent lists + weight transpose ----------------
// block 0                  : sym table
// blocks 1..NB             : per-image absent lists
// blocks NB+1 .. +NJT*NDT  : transpose tiles 32j x 128d (16 LDGs in flight/thread)
__global__ void k_setup(const void* __restrict__ pairs_v,
                        const float* __restrict__ score,
                        const float* __restrict__ w) {
    const int* p32 = (const int*)pairs_v;
    int tid = threadIdx.x;
    if (blockIdx.x == 0) {
#pragma unroll 4
        for (int idx = tid; idx < NC * NC; idx += 256) {
            int c = idx / NC, e = idx % NC;
            g_sym[idx] = 0.5f * (score[c * NC + e] + score[e * NC + c]);
        }
    } else if (blockIdx.x <= NB) {
        int b = blockIdx.x - 1;
        int is64 = pairs_is64(p32);
        __shared__ int flags[NC];
        for (int i = tid; i < NC; i += 256) flags[i] = 0;
        __syncthreads();
        for (int i = tid; i < 2 * NP; i += 256) {
            size_t ei = (size_t)b * 2 * NP + i;
            flags[p32[ei << is64]] = 1;
        }
        __syncthreads();
        if (tid == 0) {
            int cnt = 0;
            for (int e = 1; e < NC; ++e)
                if (!flags[e]) g_abs_list[b * CM1 + cnt++] = e;
            g_abs_cnt[b] = cnt;
        }
    } else {
        // transpose tile: 32 j-cols x 128 d-rows of lin_w -> WT
        int t_id = blockIdx.x - (NB + 1);
        int j0 = (t_id % NJT) * 32, d0 = (t_id / NJT) * 128;
        __shared__ float t[128][33];             // t[d][j], pad 33 -> conflict-free
        int tx = tid & 31, ty = tid >> 5;        // (32, 8)
        int j = j0 + tx;
        bool jok = (j < 600);
#pragma unroll
        for (int rep = 0; rep < 16; ++rep) {     // 16 independent LDGs
            int dr = ty + 8 * rep;
            t[dr][tx] = jok ? w[(size_t)(d0 + dr) * 600 + j] : 0.f;
        }
        __syncthreads();
#pragma unroll
        for (int rep = 0; rep < 4; ++rep) {      // j-row = ty + 8*rep
            int jr = ty + 8 * rep;
            int jj = j0 + jr;
            if (jj >= 600) continue;
#pragma unroll
            for (int q = 0; q < 4; ++q)          // 32 consecutive d per warp -> 128B stores
                g_WT[(size_t)jj * DIM + d0 + q * 32 + tx] = t[q * 32 + tx][jr];
        }
    }
}

// ---------------- kernel 2: dense class tables T0/T1 ----------------
// grid (38, 2, 4), block 128. 4 classes x 128 float4-cols per block; e-loop
// unrolled x6 for memory-level parallelism.
__global__ void k_tables(const float* __restrict__ lb) {
    int which = blockIdx.y;
    int cBase = blockIdx.x * 4;
    __shared__ float ssym[4][NC + 1];
    int tid = threadIdx.x;
    for (int idx = tid; idx < 4 * NC; idx += 128) {
        int ci = idx / NC, e = idx % NC;
        int c = cBase + ci;
        ssym[ci][e] = (c < NC) ? g_sym[c * NC + e] : 0.f;
    }
    __syncthreads();
    const float4* WT4 = (const float4*)g_WT;
    int d4 = blockIdx.z * 128 + tid;             // 0..511
    float4 acc[4];
#pragma unroll
    for (int ci = 0; ci < 4; ++ci) acc[ci] = make_float4(0.f, 0.f, 0.f, 0.f);
    int base = which * CM1;
#pragma unroll 6
    for (int e = 1; e < NC; ++e) {
        float4 wv = WT4[(size_t)(base + e - 1) * (DIM / 4) + d4];
#pragma unroll
        for (int ci = 0; ci < 4; ++ci) acc[ci] = f4fma(ssym[ci][e], wv, acc[ci]);
    }
    float4 hb = ((const float4*)lb)[d4];
    hb.x *= 0.5f; hb.y *= 0.5f; hb.z *= 0.5f; hb.w *= 0.5f;
    float* Tdst = which ? g_T1 : g_T0;
#pragma unroll
    for (int ci = 0; ci < 4; ++ci) {
        int c = cBase + ci;
        if (c >= NC) continue;
        float4 v = f4add(acc[ci], hb);
        if (c >= 1) {
            float4 pv = WT4[(size_t)(300 + which * CM1 + c - 1) * (DIM / 4) + d4];
            v = f4add(v, pv);
        }
        ((float4*)Tdst)[(size_t)c * (DIM / 4) + d4] = v;
    }
}

// ---------------- rare exact fallback (keeps main loop register-lean) ----------------
__device__ __noinline__ float4 fallback_corr(float4 v, int b, int p0, int p1,
                                             int cb, int j, int cnt) {
    const float4* WT4 = (const float4*)g_WT;
    for (int k = CAP; k < cnt; ++k) {
        int e = g_abs_list[b * CM1 + k];
        float4 a  = WT4[(size_t)(e - 1) * (DIM / 4) + cb + j];
        float4 bb = WT4[(size_t)(CM1 + e - 1) * (DIM / 4) + cb + j];
        v = f4fms(g_sym[p0 * NC + e], a, v);
        v = f4fms(g_sym[p1 * NC + e], bb, v);
    }
    return v;
}

// ---------------- kernel 3: persistent gather/add ----------------
// grid 296 (2 blocks/SM), 1024 threads, ~89.7KB dynamic smem each.
__global__ void __launch_bounds__(TPB, 2) k_main(const void* __restrict__ pairs_v,
                                                 float* __restrict__ out) {
    extern __shared__ float4 smem[];
    float4* s0 = smem;                       // NC*CHW
    float4* s1 = s0 + NC * CHW;              // NC*CHW
    float4* wa = s1 + NC * CHW;              // CAP*CHW
    float4* wb = wa + CAP * CHW;             // CAP*CHW
    int* sp = (int*)(wb + CAP * CHW);        // 2*NP = 1024
    int* slist = sp + 2 * NP;                // CAP
    __shared__ int scnt;

    const int* p32 = (const int*)pairs_v;
    int is64 = pairs_is64(p32);
    int tid = threadIdx.x;
    const float4* T04 = (const float4*)g_T0;
    const float4* T14 = (const float4*)g_T1;
    const float4* WT4 = (const float4*)g_WT;
    float4* out4 = (float4*)out;

    const int nitems = NCHUNK * NB;          // 4096
    int start = (int)(((long)nitems * blockIdx.x) / gridDim.x);
    int end   = (int)(((long)nitems * (blockIdx.x + 1)) / gridDim.x);
    int cur_chunk = -1;

    for (int item = start; item < end; ++item) {
        int chunk = item >> 7;               // item / NB
        int b = item & (NB - 1);
        int cb = chunk * CHW;

        __syncthreads();                     // protect smem reuse from prior item
        if (chunk != cur_chunk) {
            for (int idx = tid; idx < NC * CHW; idx += TPB) {
                int c = idx / CHW, j = idx % CHW;
                s0[idx] = T04[(size_t)c * (DIM / 4) + cb + j];
                s1[idx] = T14[(size_t)c * (DIM / 4) + cb + j];
            }
            cur_chunk = chunk;
        }
        sp[tid] = p32[((size_t)b * 2 * NP + tid) << is64];
        if (tid < CAP) slist[tid] = g_abs_list[b * CM1 + tid];
        if (tid == 0) scnt = g_abs_cnt[b];
        __syncthreads();

        int cnt = scnt;
        int kc = cnt < CAP ? cnt : CAP;
        for (int idx = tid; idx < kc * CHW; idx += TPB) {
            int k = idx / CHW, j = idx % CHW;
            int e = slist[k];
            wa[idx] = WT4[(size_t)(e - 1) * (DIM / 4) + cb + j];
            wb[idx] = WT4[(size_t)(CM1 + e - 1) * (DIM / 4) + cb + j];
        }
        if (kc) __syncthreads();

        int j = tid & (CHW - 1), sub = tid >> 4;   // sub in 0..63
#pragma unroll 4
        for (int it = 0; it < NP / 64; ++it) {
            int p = it * 64 + sub;
            int p0 = sp[2 * p], p1 = sp[2 * p + 1];
            float4 v = f4add(s0[p0 * CHW + j], s1[p1 * CHW + j]);
            for (int k = 0; k < kc; ++k) {
                int e = slist[k];
                v = f4fms(g_sym[p0 * NC + e], wa[k * CHW + j], v);
                v = f4fms(g_sym[p1 * NC + e], wb[k * CHW + j], v);
            }
            if (cnt > CAP) v = fallback_corr(v, b, p0, p1, cb, j, cnt);
            __stcs(&out4[(size_t)(b * NP + p) * (DIM / 4) + cb + j], v);
        }
    }
}

// ---------------- launch ----------------
static const size_t SMEM_MAIN =
    (size_t)(2 * NC * CHW + 2 * CAP * CHW) * sizeof(float4) + (2 * NP + CAP) * sizeof(int);

extern "C" void kernel_launch(void* const* d_in, const int* in_sizes, int n_in,
                              void* d_out, int out_size) {
    const void*  pairs = d_in[0];
    const float* score = (const float*)d_in[1];
    const float* lw    = (const float*)d_in[2];
    const float* lb    = (const float*)d_in[3];
    float* out = (float*)d_out;
    (void)in_sizes; (void)n_in; (void)out_size;

    cudaFuncSetAttribute(k_main, cudaFuncAttributeMaxDynamicSharedMemorySize, (int)SMEM_MAIN);

    k_setup <<<NB + 1 + NJT * NDT, 256>>>(pairs, score, lw);
    k_tables<<<dim3(38, 2, 4), 128>>>(lb);
    k_main  <<<296, TPB, SMEM_MAIN>>>(pairs, out);
}